// round 4
// baseline (speedup 1.0000x reference)
#include <cuda_runtime.h>
#include <math.h>

#define HH 256
#define NP 32
#define LL 8192
#define LH 4097           // L/2 + 1
#define M2 4096           // L/2  (packed real-IFFT size)
#define ROW 4098          // padded k_f row stride (keeps rows 16B-aligned)
#define ILP 4             // node-pairs per thread in cauchy

#ifndef PI_D
#define PI_D 3.14159265358979323846
#endif

// scratch: k_f spectrum, one padded row per head (complex)
__device__ float2 g_kf[HH * ROW];

// ---------------- packed f32x2 helpers (sm_100+) ----------------
typedef unsigned long long u64;

__device__ __forceinline__ u64 pk2(float lo, float hi) {
    u64 r; asm("mov.b64 %0, {%1,%2};" : "=l"(r) : "f"(lo), "f"(hi)); return r;
}
__device__ __forceinline__ void upk2(u64 v, float& lo, float& hi) {
    asm("mov.b64 {%0,%1}, %2;" : "=f"(lo), "=f"(hi) : "l"(v));
}
__device__ __forceinline__ u64 fma2(u64 a, u64 b, u64 c) {
    u64 d; asm("fma.rn.f32x2 %0,%1,%2,%3;" : "=l"(d) : "l"(a), "l"(b), "l"(c)); return d;
}
__device__ __forceinline__ u64 add2(u64 a, u64 b) {
    u64 d; asm("add.rn.f32x2 %0,%1,%2;" : "=l"(d) : "l"(a), "l"(b)); return d;
}
__device__ __forceinline__ u64 mul2(u64 a, u64 b) {
    u64 d; asm("mul.rn.f32x2 %0,%1,%2;" : "=l"(d) : "l"(a), "l"(b)); return d;
}
__device__ __forceinline__ u64 rcp2(u64 a) {
    float lo, hi, rl, rh;
    upk2(a, lo, hi);
    asm("rcp.approx.f32 %0,%1;" : "=f"(rl) : "f"(lo));
    asm("rcp.approx.f32 %0,%1;" : "=f"(rh) : "f"(hi));
    return pk2(rl, rh);
}

// y = 2*tan(pi*l/L); double path near the Nyquist pole where float arg error
// is amplified by 1/(pi/2 - x).
__device__ __forceinline__ float y_of(int l) {
    if (l >= LH) l = LH - 1;                 // clamp dummy lanes
    if (l < 3968) return 2.0f * tanf((float)l * (float)(PI_D / (double)LL));
    return (float)(2.0 * tan((PI_D / (double)LL) * (double)l));
}

// ---------------------------------------------------------------------------
// Kernel A: Cauchy sums + Woodbury -> k_f[h][l].
// Each thread handles ILP=4 node-pairs (8 frequencies) in packed f32x2.
// grid = (3, H), block = 256  (3*256*ILP = 3072 >= 2049 pairs).
// ---------------------------------------------------------------------------
__global__ __launch_bounds__(256) void cauchy_kernel(
    const float* __restrict__ w_re, const float* __restrict__ w_im,
    const float* __restrict__ p_re, const float* __restrict__ p_im,
    const float* __restrict__ B_re, const float* __restrict__ B_im,
    const float* __restrict__ C_re, const float* __restrict__ C_im,
    const float* __restrict__ log_dt)
{
    __shared__ float4 shf[NP][3];
    __shared__ float sh_dt;

    const int h   = blockIdx.y;
    const int tid = threadIdx.x;

    if (tid < NP) {
        const float dt = expf(log_dt[h]);
        if (tid == 0) sh_dt = dt;
        const int idx = h * NP + tid;
        const float a  = w_re[idx] * dt;      // fold dt into pole
        const float b  = w_im[idx] * dt;
        const float Br = B_re[idx], Bi = B_im[idx];
        const float Pr = p_re[idx], Pi = p_im[idx];
        const float Cr = C_re[idx], Ci = C_im[idx];
        shf[tid][0] = make_float4(a * a, b, a, Pr * Pr + Pi * Pi);
        shf[tid][1] = make_float4(Br * Cr - Bi * Ci,  // v00r = (B*C).re
                                  Br * Ci + Bi * Cr,  // v00i
                                  Br * Pr + Bi * Pi,  // v01r = (B*conj P).re
                                  Bi * Pr - Br * Pi); // v01i
        shf[tid][2] = make_float4(Pr * Cr - Pi * Ci,  // v10r = (P*C).re
                                  Pr * Ci + Pi * Cr,  // v10i
                                  0.f, 0.f);
    }
    __syncthreads();

    // pair indices: p[k] = blk*1024 + tid + 256k  (coalesced stores per k)
    int p[ILP];
    u64 yy[ILP];
    float ylo[ILP], yhi[ILP];
#pragma unroll
    for (int k = 0; k < ILP; k++) {
        p[k] = blockIdx.x * (256 * ILP) + tid + 256 * k;
        const int l0 = 2 * p[k];
        ylo[k] = y_of(l0);
        yhi[k] = y_of(l0 + 1);
        yy[k] = pk2(ylo[k], yhi[k]);
    }

    const u64 m1 = pk2(-1.0f, -1.0f);
    u64 r00r[ILP] = {0,0,0,0}, r00i[ILP] = {0,0,0,0};
    u64 r01r[ILP] = {0,0,0,0}, r01i[ILP] = {0,0,0,0};
    u64 r10r[ILP] = {0,0,0,0}, r10i[ILP] = {0,0,0,0};
    u64 r11r[ILP] = {0,0,0,0}, r11i[ILP] = {0,0,0,0};

#pragma unroll 4
    for (int n = 0; n < NP; n++) {
        const float4 f0 = shf[n][0];
        const float4 f1 = shf[n][1];
        const float4 f2 = shf[n][2];
        const u64 A2  = pk2(f0.x, f0.x);
        const u64 Bb  = pk2(f0.y, f0.y);
        const u64 nBb = pk2(-f0.y, -f0.y);
        const u64 Aa  = pk2(f0.z, f0.z);
        const u64 nAa = pk2(-f0.z, -f0.z);
        const u64 V11 = pk2(f0.w, f0.w);
        const u64 V00r = pk2(f1.x, f1.x), V00i = pk2(f1.y, f1.y);
        const u64 V01r = pk2(f1.z, f1.z), V01i = pk2(f1.w, f1.w);
        const u64 V10r = pk2(f2.x, f2.x), V10i = pk2(f2.y, f2.y);

#pragma unroll
        for (int k = 0; k < ILP; k++) {
            const u64 t1 = add2(yy[k], nBb);               // y - b
            const u64 t2 = add2(yy[k], Bb);                // y + b
            const u64 inv1 = rcp2(fma2(t1, t1, A2));       // 1/(t1^2 + a^2)
            const u64 inv2 = rcp2(fma2(t2, t2, A2));
            const u64 u1 = mul2(t1, inv1);
            const u64 u2 = mul2(t2, inv2);
            const u64 Sr = mul2(nAa, add2(inv1, inv2));    // -a*(inv1+inv2)
            const u64 Dr = mul2(Aa,  fma2(inv1, m1, inv2));//  a*(inv2-inv1)
            const u64 Si = mul2(add2(u1, u2), m1);         // -(u1+u2)
            const u64 Di = fma2(u2, m1, u1);               //  u1-u2

            r00r[k] = fma2(V00r, Sr, fma2(V00i, Di, r00r[k]));
            r00i[k] = fma2(V00r, Si, fma2(V00i, Dr, r00i[k]));
            r01r[k] = fma2(V01r, Sr, fma2(V01i, Di, r01r[k]));
            r01i[k] = fma2(V01r, Si, fma2(V01i, Dr, r01i[k]));
            r10r[k] = fma2(V10r, Sr, fma2(V10i, Di, r10r[k]));
            r10i[k] = fma2(V10r, Si, fma2(V10i, Dr, r10i[k]));
            r11r[k] = fma2(V11, Sr, r11r[k]);
            r11i[k] = fma2(V11, Si, r11i[k]);
        }
    }

    const float dt = sh_dt;
    float2* row = g_kf + h * ROW;

#pragma unroll
    for (int k = 0; k < ILP; k++) {
        if (p[k] > 2048) continue;            // beyond LH
        float b00r[2], b00i[2], b01r[2], b01i[2], b10r[2], b10i[2], b11r[2], b11i[2];
        upk2(r00r[k], b00r[0], b00r[1]); upk2(r00i[k], b00i[0], b00i[1]);
        upk2(r01r[k], b01r[0], b01r[1]); upk2(r01i[k], b01i[0], b01i[1]);
        upk2(r10r[k], b10r[0], b10r[1]); upk2(r10i[k], b10i[0], b10i[1]);
        upk2(r11r[k], b11r[0], b11r[1]); upk2(r11i[k], b11i[0], b11i[1]);

        float2 res[2];
        const float yv[2] = {ylo[k], yhi[k]};
#pragma unroll
        for (int s = 0; s < 2; s++) {
            const float q00r = b00r[s] * dt, q00i = b00i[s] * dt;
            const float q01r = b01r[s] * dt, q01i = b01i[s] * dt;
            const float q10r = b10r[s] * dt, q10i = b10i[s] * dt;
            const float q11r = b11r[s] * dt, q11i = b11i[s] * dt;
            // Woodbury: k_f = (r00 - r01*r10/(1+r11)) * (1 + i*y/2)
            const float drw = 1.f + q11r, diw = q11i;
            float invd; asm("rcp.approx.f32 %0,%1;" : "=f"(invd) : "f"(fmaf(drw, drw, diw * diw)));
            const float numr = q01r * q10r - q01i * q10i;
            const float numi = q01r * q10i + q01i * q10r;
            const float cr = (numr * drw + numi * diw) * invd;
            const float ci = (numi * drw - numr * diw) * invd;
            const float ar = q00r - cr, ai = q00i - ci;
            const float g = 0.5f * yv[s];
            res[s] = make_float2(fmaf(-ai, g, ar), fmaf(ar, g, ai));
        }

        const int l0 = 2 * p[k];
        if (p[k] < 2048) {
            *reinterpret_cast<float4*>(row + l0) =
                make_float4(res[0].x, res[0].y, res[1].x, res[1].y);
        } else {
            row[l0] = res[0];                 // l0 == 4096 tail
        }
    }
}

// ---------------------------------------------------------------------------
// helpers for the FFT
// ---------------------------------------------------------------------------
__device__ __forceinline__ float2 cmul(float2 a, float2 b) {
    return make_float2(a.x * b.x - a.y * b.y, a.x * b.y + a.y * b.x);
}
__device__ __forceinline__ int dr4(int k) {   // base-4 digit reversal of 12-bit index
    unsigned r = __brev((unsigned)k) >> 20;
    return (int)(((r & 0x555u) << 1) | ((r >> 1) & 0x555u));
}

// ---------------------------------------------------------------------------
// Kernel B: irfft(k_f) per head via packed real-IFFT, radix-4 DIT in shared.
// Twiddles computed on the fly (__sincosf on the idle MUFU pipe).
// grid = H blocks, 512 threads, 32 KB dynamic shared -> 4 blocks/SM.
// ---------------------------------------------------------------------------
__global__ __launch_bounds__(512) void ifft_kernel(float* __restrict__ out)
{
    extern __shared__ float2 spec[];   // 4096 complex (32 KB)

    const int h   = blockIdx.x;
    const int tid = threadIdx.x;

    // Hermitian pack with 1/M scale folded in, base-4 digit-reversed layout.
    const float sc = 0.5f / (float)M2;
    const float2* kf = g_kf + h * ROW;
    for (int k = tid; k <= M2 / 2; k += blockDim.x) {
        const float2 Xk = kf[k];
        const float2 Xm = kf[M2 - k];
        const float mr = Xm.x, mi = -Xm.y;            // conj(X[M-k])
        const float Er = sc * (Xk.x + mr);
        const float Ei = sc * (Xk.y + mi);
        const float Fr = sc * (Xk.x - mr);
        const float Fi = sc * (Xk.y - mi);
        float s, c;
        __sincosf((float)k * (float)(PI_D / (double)M2), &s, &c); // e^{+i*pi*k/M}
        const float Or = c * Fr - s * Fi;
        const float Oi = c * Fi + s * Fr;
        spec[dr4(k)] = make_float2(Er - Oi, Ei + Or);
        if (k > 0 && k < M2 / 2) {
            spec[dr4(M2 - k)] = make_float2(Er + Oi, Or - Ei);
        }
    }
    __syncthreads();

    // Stage 0 (q = 1): all twiddles are 1.
    for (int j = tid; j < M2 / 4; j += blockDim.x) {
        const int i0 = j << 2;
        const float2 x0 = spec[i0], x1 = spec[i0 + 1], x2 = spec[i0 + 2], x3 = spec[i0 + 3];
        const float apx = x0.x + x2.x, apy = x0.y + x2.y;
        const float amx = x0.x - x2.x, amy = x0.y - x2.y;
        const float bpx = x1.x + x3.x, bpy = x1.y + x3.y;
        const float bmx = x1.x - x3.x, bmy = x1.y - x3.y;
        spec[i0]     = make_float2(apx + bpx, apy + bpy);
        spec[i0 + 1] = make_float2(amx - bmy, amy + bmx);   // am + i*bm
        spec[i0 + 2] = make_float2(apx - bpx, apy - bpy);
        spec[i0 + 3] = make_float2(amx + bmy, amy - bmx);   // am - i*bm
    }
    __syncthreads();

    // Stages 1..5: q = 4, 16, 64, 256, 1024. Twiddles e^{+i*2*pi*tb/4096}.
#pragma unroll 1
    for (int st = 1; st < 6; st++) {
        const int q    = 1 << (2 * st);
        const int tsh  = 10 - 2 * st;       // twiddle stride shift: 1024/q
        for (int j = tid; j < M2 / 4; j += blockDim.x) {
            const int pos = j & (q - 1);
            const int i0  = ((j >> (2 * st)) << (2 * st + 2)) | pos;
            const int tb  = pos << tsh;
            float s1, c1;
            __sincosf((float)tb * (float)(2.0 * PI_D / (double)M2), &s1, &c1);
            const float2 w1 = make_float2(c1, s1);
            const float2 w2 = cmul(w1, w1);
            const float2 w3 = cmul(w2, w1);
            const float2 x0 = spec[i0];
            const float2 b  = cmul(spec[i0 + q],     w1);
            const float2 c  = cmul(spec[i0 + 2 * q], w2);
            const float2 d  = cmul(spec[i0 + 3 * q], w3);
            const float apx = x0.x + c.x, apy = x0.y + c.y;
            const float amx = x0.x - c.x, amy = x0.y - c.y;
            const float bpx = b.x + d.x,  bpy = b.y + d.y;
            const float bmx = b.x - d.x,  bmy = b.y - d.y;
            spec[i0]         = make_float2(apx + bpx, apy + bpy);
            spec[i0 + q]     = make_float2(amx - bmy, amy + bmx);
            spec[i0 + 2 * q] = make_float2(apx - bpx, apy - bpy);
            spec[i0 + 3 * q] = make_float2(amx + bmy, amy - bmx);
        }
        __syncthreads();
    }

    // z[t] = x[2t] + i*x[2t+1], already scaled. Coalesced float2 stores.
    float2* outv = (float2*)out + h * M2;
    for (int t = tid; t < M2; t += blockDim.x) {
        outv[t] = spec[t];
    }
}

// ---------------------------------------------------------------------------
extern "C" void kernel_launch(void* const* d_in, const int* in_sizes, int n_in,
                              void* d_out, int out_size)
{
    const float* w_re   = (const float*)d_in[0];
    const float* w_im   = (const float*)d_in[1];
    const float* p_re   = (const float*)d_in[2];
    const float* p_im   = (const float*)d_in[3];
    const float* B_re   = (const float*)d_in[4];
    const float* B_im   = (const float*)d_in[5];
    const float* C_re   = (const float*)d_in[6];
    const float* C_im   = (const float*)d_in[7];
    const float* log_dt = (const float*)d_in[8];

    dim3 gridA(3, HH);      // 3*256*ILP = 3072 >= 2049 node-pairs per head
    cauchy_kernel<<<gridA, 256>>>(w_re, w_im, p_re, p_im,
                                  B_re, B_im, C_re, C_im, log_dt);

    ifft_kernel<<<HH, 512, M2 * sizeof(float2)>>>((float*)d_out);
}

// round 5
// speedup vs baseline: 1.2522x; 1.2522x over previous
#include <cuda_runtime.h>
#include <math.h>

#define HH 256
#define NP 32
#define LL 8192
#define LH 4097           // L/2 + 1
#define M2 4096           // L/2  (packed real-IFFT size)
#define ROW 4098          // padded k_f row stride (keeps rows 16B-aligned)

#ifndef PI_D
#define PI_D 3.14159265358979323846
#endif

// scratch: k_f spectrum, one padded row per head (complex)
__device__ float2 g_kf[HH * ROW];

// ---------------- packed f32x2 helpers (sm_100+) ----------------
typedef unsigned long long u64;

__device__ __forceinline__ u64 pk2(float lo, float hi) {
    u64 r; asm("mov.b64 %0, {%1,%2};" : "=l"(r) : "f"(lo), "f"(hi)); return r;
}
__device__ __forceinline__ void upk2(u64 v, float& lo, float& hi) {
    asm("mov.b64 {%0,%1}, %2;" : "=f"(lo), "=f"(hi) : "l"(v));
}
__device__ __forceinline__ u64 fma2(u64 a, u64 b, u64 c) {
    u64 d; asm("fma.rn.f32x2 %0,%1,%2,%3;" : "=l"(d) : "l"(a), "l"(b), "l"(c)); return d;
}
__device__ __forceinline__ u64 add2(u64 a, u64 b) {
    u64 d; asm("add.rn.f32x2 %0,%1,%2;" : "=l"(d) : "l"(a), "l"(b)); return d;
}
__device__ __forceinline__ u64 mul2(u64 a, u64 b) {
    u64 d; asm("mul.rn.f32x2 %0,%1,%2;" : "=l"(d) : "l"(a), "l"(b)); return d;
}
__device__ __forceinline__ u64 rcp2(u64 a) {
    float lo, hi, rl, rh;
    upk2(a, lo, hi);
    asm("rcp.approx.f32 %0,%1;" : "=f"(rl) : "f"(lo));
    asm("rcp.approx.f32 %0,%1;" : "=f"(rh) : "f"(hi));
    return pk2(rl, rh);
}

// y = 2*tan(pi*l/L); double path near the Nyquist pole where float arg error
// is amplified by 1/(pi/2 - x).
__device__ __forceinline__ float y_of(int l) {
    if (l >= LH) l = LH - 1;                 // clamp dummy lanes
    if (l < 3968) return 2.0f * tanf((float)l * (float)(PI_D / (double)LL));
    return (float)(2.0 * tan((PI_D / (double)LL) * (double)l));
}

// ---------------------------------------------------------------------------
// Kernel A: Cauchy sums + Woodbury -> k_f[h][l].
// ILP=2: each thread handles pairs gid and gid+1056 (4 frequencies total).
// grid = (3, H), block = 352  (3*352 = 1056 threads; 2*1056 = 2112 >= 2049).
// Constants pre-duplicated in shared as f32x2 pairs; dt folded into v.
// ---------------------------------------------------------------------------
__global__ __launch_bounds__(352) void cauchy_kernel(
    const float* __restrict__ w_re, const float* __restrict__ w_im,
    const float* __restrict__ p_re, const float* __restrict__ p_im,
    const float* __restrict__ B_re, const float* __restrict__ B_im,
    const float* __restrict__ C_re, const float* __restrict__ C_im,
    const float* __restrict__ log_dt)
{
    // per-pole packed constants, each ulonglong2 = two f32x2 values
    __shared__ ulonglong2 sh[NP][6];

    const int h   = blockIdx.y;
    const int tid = threadIdx.x;

    if (tid < NP) {
        const float dt = expf(log_dt[h]);
        const int idx = h * NP + tid;
        const float a  = w_re[idx] * dt;      // fold dt into pole
        const float b  = w_im[idx] * dt;
        const float Br = B_re[idx], Bi = B_im[idx];
        const float Pr = p_re[idx], Pi = p_im[idx];
        const float Cr = C_re[idx], Ci = C_im[idx];
        // v-coefficients pre-scaled by dt (r enters Woodbury as dt * sums)
        const float v00r = (Br * Cr - Bi * Ci) * dt, v00i = (Br * Ci + Bi * Cr) * dt;
        const float v01r = (Br * Pr + Bi * Pi) * dt, v01i = (Bi * Pr - Br * Pi) * dt;
        const float v10r = (Pr * Cr - Pi * Ci) * dt, v10i = (Pr * Ci + Pi * Cr) * dt;
        const float v11  = (Pr * Pr + Pi * Pi) * dt;
        sh[tid][0] = make_ulonglong2(pk2(a * a, a * a), pk2(b, b));
        sh[tid][1] = make_ulonglong2(pk2(-b, -b),      pk2(a, a));
        sh[tid][2] = make_ulonglong2(pk2(-a, -a),      pk2(v11, v11));
        sh[tid][3] = make_ulonglong2(pk2(v00r, v00r),  pk2(v00i, v00i));
        sh[tid][4] = make_ulonglong2(pk2(v01r, v01r),  pk2(v01i, v01i));
        sh[tid][5] = make_ulonglong2(pk2(v10r, v10r),  pk2(v10i, v10i));
    }
    __syncthreads();

    const int gid = blockIdx.x * 352 + tid;
    int p[2];
    p[0] = gid;                 // pairs 0..1055
    p[1] = gid + 1056;          // pairs 1056..2111 (>2048 are dummies)

    u64 yy[2];
    float ylo[2], yhi[2];
#pragma unroll
    for (int k = 0; k < 2; k++) {
        const int l0 = 2 * p[k];
        ylo[k] = y_of(l0);
        yhi[k] = y_of(l0 + 1);
        yy[k] = pk2(ylo[k], yhi[k]);
    }

    const u64 m1 = pk2(-1.0f, -1.0f);
    u64 r00r[2] = {0,0}, r00i[2] = {0,0};
    u64 r01r[2] = {0,0}, r01i[2] = {0,0};
    u64 r10r[2] = {0,0}, r10i[2] = {0,0};
    u64 r11r[2] = {0,0}, r11i[2] = {0,0};

#pragma unroll 8
    for (int n = 0; n < NP; n++) {
        const ulonglong2 e0 = sh[n][0];   // a2 | b
        const ulonglong2 e1 = sh[n][1];   // -b | a
        const ulonglong2 e2 = sh[n][2];   // -a | v11
        const ulonglong2 e3 = sh[n][3];   // v00r | v00i
        const ulonglong2 e4 = sh[n][4];   // v01r | v01i
        const ulonglong2 e5 = sh[n][5];   // v10r | v10i

#pragma unroll
        for (int k = 0; k < 2; k++) {
            const u64 t1 = add2(yy[k], e1.x);              // y - b
            const u64 t2 = add2(yy[k], e0.y);              // y + b
            const u64 inv1 = rcp2(fma2(t1, t1, e0.x));     // 1/(t1^2 + a^2)
            const u64 inv2 = rcp2(fma2(t2, t2, e0.x));
            const u64 u1 = mul2(t1, inv1);
            const u64 u2 = mul2(t2, inv2);
            const u64 Sr = mul2(e2.x, add2(inv1, inv2));   // -a*(inv1+inv2)
            const u64 Dr = mul2(e1.y, fma2(inv1, m1, inv2)); //  a*(inv2-inv1)
            const u64 Si = mul2(add2(u1, u2), m1);         // -(u1+u2)
            const u64 Di = fma2(u2, m1, u1);               //  u1-u2

            r00r[k] = fma2(e3.x, Sr, fma2(e3.y, Di, r00r[k]));
            r00i[k] = fma2(e3.x, Si, fma2(e3.y, Dr, r00i[k]));
            r01r[k] = fma2(e4.x, Sr, fma2(e4.y, Di, r01r[k]));
            r01i[k] = fma2(e4.x, Si, fma2(e4.y, Dr, r01i[k]));
            r10r[k] = fma2(e5.x, Sr, fma2(e5.y, Di, r10r[k]));
            r10i[k] = fma2(e5.x, Si, fma2(e5.y, Dr, r10i[k]));
            r11r[k] = fma2(e2.y, Sr, r11r[k]);
            r11i[k] = fma2(e2.y, Si, r11i[k]);
        }
    }

    float2* row = g_kf + h * ROW;

#pragma unroll
    for (int k = 0; k < 2; k++) {
        if (p[k] > 2048) continue;            // dummy tail pairs
        float b00r[2], b00i[2], b01r[2], b01i[2], b10r[2], b10i[2], b11r[2], b11i[2];
        upk2(r00r[k], b00r[0], b00r[1]); upk2(r00i[k], b00i[0], b00i[1]);
        upk2(r01r[k], b01r[0], b01r[1]); upk2(r01i[k], b01i[0], b01i[1]);
        upk2(r10r[k], b10r[0], b10r[1]); upk2(r10i[k], b10i[0], b10i[1]);
        upk2(r11r[k], b11r[0], b11r[1]); upk2(r11i[k], b11i[0], b11i[1]);

        float2 res[2];
        const float yv[2] = {ylo[k], yhi[k]};
#pragma unroll
        for (int s = 0; s < 2; s++) {
            // dt already folded into accumulators via v.
            // Woodbury: k_f = (r00 - r01*r10/(1+r11)) * (1 + i*y/2)
            const float drw = 1.f + b11r[s], diw = b11i[s];
            float invd; asm("rcp.approx.f32 %0,%1;" : "=f"(invd) : "f"(fmaf(drw, drw, diw * diw)));
            const float numr = b01r[s] * b10r[s] - b01i[s] * b10i[s];
            const float numi = b01r[s] * b10i[s] + b01i[s] * b10r[s];
            const float cr = (numr * drw + numi * diw) * invd;
            const float ci = (numi * drw - numr * diw) * invd;
            const float ar = b00r[s] - cr, ai = b00i[s] - ci;
            const float g = 0.5f * yv[s];
            res[s] = make_float2(fmaf(-ai, g, ar), fmaf(ar, g, ai));
        }

        const int l0 = 2 * p[k];
        if (p[k] < 2048) {
            *reinterpret_cast<float4*>(row + l0) =
                make_float4(res[0].x, res[0].y, res[1].x, res[1].y);
        } else {
            row[l0] = res[0];                 // l0 == 4096 tail
        }
    }
}

// ---------------------------------------------------------------------------
// helpers for the FFT
// ---------------------------------------------------------------------------
__device__ __forceinline__ float2 cmul(float2 a, float2 b) {
    return make_float2(a.x * b.x - a.y * b.y, a.x * b.y + a.y * b.x);
}
__device__ __forceinline__ int dr4(int k) {   // base-4 digit reversal of 12-bit index
    unsigned r = __brev((unsigned)k) >> 20;
    return (int)(((r & 0x555u) << 1) | ((r >> 1) & 0x555u));
}

// ---------------------------------------------------------------------------
// Kernel B: irfft(k_f) per head via packed real-IFFT, radix-4 DIT in shared.
// Twiddles computed on the fly (__sincosf on the idle MUFU pipe).
// grid = H blocks, 1024 threads, 32 KB dynamic shared.
// ---------------------------------------------------------------------------
__global__ __launch_bounds__(1024) void ifft_kernel(float* __restrict__ out)
{
    extern __shared__ float2 spec[];   // 4096 complex (32 KB)

    const int h   = blockIdx.x;
    const int tid = threadIdx.x;

    // Hermitian pack with 1/M scale folded in, base-4 digit-reversed layout.
    const float sc = 0.5f / (float)M2;
    const float2* kf = g_kf + h * ROW;
    for (int k = tid; k <= M2 / 2; k += blockDim.x) {
        const float2 Xk = kf[k];
        const float2 Xm = kf[M2 - k];
        const float mr = Xm.x, mi = -Xm.y;            // conj(X[M-k])
        const float Er = sc * (Xk.x + mr);
        const float Ei = sc * (Xk.y + mi);
        const float Fr = sc * (Xk.x - mr);
        const float Fi = sc * (Xk.y - mi);
        float s, c;
        __sincosf((float)k * (float)(PI_D / (double)M2), &s, &c); // e^{+i*pi*k/M}
        const float Or = c * Fr - s * Fi;
        const float Oi = c * Fi + s * Fr;
        spec[dr4(k)] = make_float2(Er - Oi, Ei + Or);
        if (k > 0 && k < M2 / 2) {
            spec[dr4(M2 - k)] = make_float2(Er + Oi, Or - Ei);
        }
    }
    __syncthreads();

    // Stage 0 (q = 1): all twiddles are 1.
    for (int j = tid; j < M2 / 4; j += blockDim.x) {
        const int i0 = j << 2;
        const float2 x0 = spec[i0], x1 = spec[i0 + 1], x2 = spec[i0 + 2], x3 = spec[i0 + 3];
        const float apx = x0.x + x2.x, apy = x0.y + x2.y;
        const float amx = x0.x - x2.x, amy = x0.y - x2.y;
        const float bpx = x1.x + x3.x, bpy = x1.y + x3.y;
        const float bmx = x1.x - x3.x, bmy = x1.y - x3.y;
        spec[i0]     = make_float2(apx + bpx, apy + bpy);
        spec[i0 + 1] = make_float2(amx - bmy, amy + bmx);   // am + i*bm
        spec[i0 + 2] = make_float2(apx - bpx, apy - bpy);
        spec[i0 + 3] = make_float2(amx + bmy, amy - bmx);   // am - i*bm
    }
    __syncthreads();

    // Stages 1..5: q = 4, 16, 64, 256, 1024. Twiddles e^{+i*2*pi*tb/4096}.
#pragma unroll 1
    for (int st = 1; st < 6; st++) {
        const int q    = 1 << (2 * st);
        const int tsh  = 10 - 2 * st;       // twiddle stride shift: 1024/q
        for (int j = tid; j < M2 / 4; j += blockDim.x) {
            const int pos = j & (q - 1);
            const int i0  = ((j >> (2 * st)) << (2 * st + 2)) | pos;
            const int tb  = pos << tsh;
            float s1, c1;
            __sincosf((float)tb * (float)(2.0 * PI_D / (double)M2), &s1, &c1);
            const float2 w1 = make_float2(c1, s1);
            const float2 w2 = cmul(w1, w1);
            const float2 w3 = cmul(w2, w1);
            const float2 x0 = spec[i0];
            const float2 b  = cmul(spec[i0 + q],     w1);
            const float2 c  = cmul(spec[i0 + 2 * q], w2);
            const float2 d  = cmul(spec[i0 + 3 * q], w3);
            const float apx = x0.x + c.x, apy = x0.y + c.y;
            const float amx = x0.x - c.x, amy = x0.y - c.y;
            const float bpx = b.x + d.x,  bpy = b.y + d.y;
            const float bmx = b.x - d.x,  bmy = b.y - d.y;
            spec[i0]         = make_float2(apx + bpx, apy + bpy);
            spec[i0 + q]     = make_float2(amx - bmy, amy + bmx);
            spec[i0 + 2 * q] = make_float2(apx - bpx, apy - bpy);
            spec[i0 + 3 * q] = make_float2(amx + bmy, amy - bmx);
        }
        __syncthreads();
    }

    // z[t] = x[2t] + i*x[2t+1], already scaled. Coalesced float2 stores.
    float2* outv = (float2*)out + h * M2;
    for (int t = tid; t < M2; t += blockDim.x) {
        outv[t] = spec[t];
    }
}

// ---------------------------------------------------------------------------
extern "C" void kernel_launch(void* const* d_in, const int* in_sizes, int n_in,
                              void* d_out, int out_size)
{
    const float* w_re   = (const float*)d_in[0];
    const float* w_im   = (const float*)d_in[1];
    const float* p_re   = (const float*)d_in[2];
    const float* p_im   = (const float*)d_in[3];
    const float* B_re   = (const float*)d_in[4];
    const float* B_im   = (const float*)d_in[5];
    const float* C_re   = (const float*)d_in[6];
    const float* C_im   = (const float*)d_in[7];
    const float* log_dt = (const float*)d_in[8];

    dim3 gridA(3, HH);      // 3 blocks x 352 threads x 2 pairs per head
    cauchy_kernel<<<gridA, 352>>>(w_re, w_im, p_re, p_im,
                                  B_re, B_im, C_re, C_im, log_dt);

    ifft_kernel<<<HH, 1024, M2 * sizeof(float2)>>>((float*)d_out);
}

// round 6
// speedup vs baseline: 1.2897x; 1.0300x over previous
#include <cuda_runtime.h>
#include <math.h>

#define HH 256
#define NP 32
#define LL 8192
#define LH 4097           // L/2 + 1
#define M2 4096           // L/2  (packed real-IFFT size)
#define ROW 4098          // padded k_f row stride (keeps rows 16B-aligned)

#ifndef PI_D
#define PI_D 3.14159265358979323846
#endif

// scratch: k_f spectrum, one padded row per head (complex)
__device__ float2 g_kf[HH * ROW];

__device__ __forceinline__ float frcp(float x) {
    float r; asm("rcp.approx.f32 %0,%1;" : "=f"(r) : "f"(x)); return r;
}

// y = 2*tan(pi*l/L); double path near the Nyquist pole where float arg error
// is amplified by 1/(pi/2 - x).
__device__ __forceinline__ float y_of(int l) {
    if (l >= LH) l = LH - 1;                 // clamp dummy lanes
    if (l < 3968) return 2.0f * tanf((float)l * (float)(PI_D / (double)LL));
    return (float)(2.0 * tan((PI_D / (double)LL) * (double)l));
}

// ---------------------------------------------------------------------------
// Kernel A: Cauchy sums + Woodbury -> k_f[h][l].
// One node-pair (2 consecutive freqs) per thread, pure scalar, 24 fma-class
// ops per (pole, freq). Per-pole constants pre-folded (a absorbed into v).
// grid = (6, H), block = 352  (6*352 = 2112 >= 2049 pairs).
// ---------------------------------------------------------------------------
__global__ __launch_bounds__(352) void cauchy_kernel(
    const float* __restrict__ w_re, const float* __restrict__ w_im,
    const float* __restrict__ p_re, const float* __restrict__ p_im,
    const float* __restrict__ B_re, const float* __restrict__ B_im,
    const float* __restrict__ C_re, const float* __restrict__ C_im,
    const float* __restrict__ log_dt)
{
    __shared__ float4 sh[NP][4];

    const int h   = blockIdx.y;
    const int tid = threadIdx.x;

    if (tid < NP) {
        const float dt = expf(log_dt[h]);
        const int idx = h * NP + tid;
        const float a  = w_re[idx] * dt;      // fold dt into pole
        const float b  = w_im[idx] * dt;
        const float Br = B_re[idx], Bi = B_im[idx];
        const float Pr = p_re[idx], Pi = p_im[idx];
        const float Cr = C_re[idx], Ci = C_im[idx];
        // v-coefficients pre-scaled by dt
        const float v00r = (Br * Cr - Bi * Ci) * dt, v00i = (Br * Ci + Bi * Cr) * dt;
        const float v01r = (Br * Pr + Bi * Pi) * dt, v01i = (Bi * Pr - Br * Pi) * dt;
        const float v10r = (Pr * Cr - Pi * Ci) * dt, v10i = (Pr * Ci + Pi * Cr) * dt;
        const float v11  = (Pr * Pr + Pi * Pi) * dt;
        // accumulation model (per freq):
        //   Pinv = inv1+inv2, Minv = inv2-inv1, Pu = u1+u2, Mu = u1-u2
        //   r_xr += (-a*vxr)*Pinv + vxi*Mu
        //   r_xi += (-vxr)*Pu    + (a*vxi)*Minv
        sh[tid][0] = make_float4(b, a * a, -a * v00r, v00i);
        sh[tid][1] = make_float4(-v00r, a * v00i, -a * v01r, v01i);
        sh[tid][2] = make_float4(-v01r, a * v01i, -a * v10r, v10i);
        sh[tid][3] = make_float4(-v10r, a * v10i, -a * v11, -v11);
    }
    __syncthreads();

    const int p = blockIdx.x * 352 + tid;     // pair index 0..2111
    if (p > 2048) return;
    const int l0 = 2 * p;

    float y[2];
    y[0] = y_of(l0);
    y[1] = y_of(l0 + 1);                      // clamped dummy at p == 2048

    float r00r[2] = {0,0}, r00i[2] = {0,0};
    float r01r[2] = {0,0}, r01i[2] = {0,0};
    float r10r[2] = {0,0}, r10i[2] = {0,0};
    float r11r[2] = {0,0}, r11i[2] = {0,0};

#pragma unroll 4
    for (int n = 0; n < NP; n++) {
        const float4 c0 = sh[n][0];   // b, a2, s00a, s00b
        const float4 c1 = sh[n][1];   // s00c, s00d, s01a, s01b
        const float4 c2 = sh[n][2];   // s01c, s01d, s10a, s10b
        const float4 c3 = sh[n][3];   // s10c, s10d, s11a, s11b

#pragma unroll
        for (int f = 0; f < 2; f++) {
            const float t1 = y[f] - c0.x;                // y - b
            const float t2 = y[f] + c0.x;                // y + b
            const float inv1 = frcp(fmaf(t1, t1, c0.y)); // 1/(t1^2 + a^2)
            const float inv2 = frcp(fmaf(t2, t2, c0.y));
            const float u1 = t1 * inv1;
            const float u2 = t2 * inv2;
            const float Pinv = inv1 + inv2;
            const float Minv = inv2 - inv1;
            const float Pu = u1 + u2;
            const float Mu = u1 - u2;

            r00r[f] = fmaf(c0.z, Pinv, fmaf(c0.w, Mu,   r00r[f]));
            r00i[f] = fmaf(c1.x, Pu,   fmaf(c1.y, Minv, r00i[f]));
            r01r[f] = fmaf(c1.z, Pinv, fmaf(c1.w, Mu,   r01r[f]));
            r01i[f] = fmaf(c2.x, Pu,   fmaf(c2.y, Minv, r01i[f]));
            r10r[f] = fmaf(c2.z, Pinv, fmaf(c2.w, Mu,   r10r[f]));
            r10i[f] = fmaf(c3.x, Pu,   fmaf(c3.y, Minv, r10i[f]));
            r11r[f] = fmaf(c3.z, Pinv, r11r[f]);
            r11i[f] = fmaf(c3.w, Pu,   r11i[f]);
        }
    }

    // Woodbury: k_f = (r00 - r01*r10/(1+r11)) * (1 + i*y/2)   (dt already in)
    float2 res[2];
#pragma unroll
    for (int s = 0; s < 2; s++) {
        const float drw = 1.f + r11r[s], diw = r11i[s];
        const float invd = frcp(fmaf(drw, drw, diw * diw));
        const float numr = r01r[s] * r10r[s] - r01i[s] * r10i[s];
        const float numi = r01r[s] * r10i[s] + r01i[s] * r10r[s];
        const float cr = (numr * drw + numi * diw) * invd;
        const float ci = (numi * drw - numr * diw) * invd;
        const float ar = r00r[s] - cr, ai = r00i[s] - ci;
        const float g = 0.5f * y[s];
        res[s] = make_float2(fmaf(-ai, g, ar), fmaf(ar, g, ai));
    }

    float2* row = g_kf + h * ROW;
    if (p < 2048) {
        *reinterpret_cast<float4*>(row + l0) =
            make_float4(res[0].x, res[0].y, res[1].x, res[1].y);
    } else {
        row[l0] = res[0];                     // l0 == 4096 tail
    }
}

// ---------------------------------------------------------------------------
// helpers for the FFT
// ---------------------------------------------------------------------------
__device__ __forceinline__ float2 cmul(float2 a, float2 b) {
    return make_float2(a.x * b.x - a.y * b.y, a.x * b.y + a.y * b.x);
}
__device__ __forceinline__ int dr4(int k) {   // base-4 digit reversal of 12-bit index
    unsigned r = __brev((unsigned)k) >> 20;
    return (int)(((r & 0x555u) << 1) | ((r >> 1) & 0x555u));
}

// ---------------------------------------------------------------------------
// Kernel B: irfft(k_f), TWO heads per block (two independent 512-thread
// halves sharing barriers). grid = 128, block = 1024, 64 KB dynamic shared.
// Radix-4 DIT, twiddles on the fly (__sincosf on the idle MUFU pipe).
// ---------------------------------------------------------------------------
__global__ __launch_bounds__(1024) void ifft_kernel(float* __restrict__ out)
{
    extern __shared__ float2 shm[];           // 2 x 4096 complex (64 KB)

    const int tid  = threadIdx.x;
    const int sub  = tid >> 9;                // 0 or 1: which head half
    const int stid = tid & 511;
    const int h    = blockIdx.x * 2 + sub;
    float2* spec = shm + sub * M2;

    // Hermitian pack with 1/M scale folded in, base-4 digit-reversed layout.
    const float sc = 0.5f / (float)M2;
    const float2* kf = g_kf + h * ROW;
    for (int k = stid; k <= M2 / 2; k += 512) {
        const float2 Xk = kf[k];
        const float2 Xm = kf[M2 - k];
        const float mr = Xm.x, mi = -Xm.y;            // conj(X[M-k])
        const float Er = sc * (Xk.x + mr);
        const float Ei = sc * (Xk.y + mi);
        const float Fr = sc * (Xk.x - mr);
        const float Fi = sc * (Xk.y - mi);
        float s, c;
        __sincosf((float)k * (float)(PI_D / (double)M2), &s, &c); // e^{+i*pi*k/M}
        const float Or = c * Fr - s * Fi;
        const float Oi = c * Fi + s * Fr;
        spec[dr4(k)] = make_float2(Er - Oi, Ei + Or);
        if (k > 0 && k < M2 / 2) {
            spec[dr4(M2 - k)] = make_float2(Er + Oi, Or - Ei);
        }
    }
    __syncthreads();

    // Stage 0 (q = 1): all twiddles are 1.
    for (int j = stid; j < M2 / 4; j += 512) {
        const int i0 = j << 2;
        const float2 x0 = spec[i0], x1 = spec[i0 + 1], x2 = spec[i0 + 2], x3 = spec[i0 + 3];
        const float apx = x0.x + x2.x, apy = x0.y + x2.y;
        const float amx = x0.x - x2.x, amy = x0.y - x2.y;
        const float bpx = x1.x + x3.x, bpy = x1.y + x3.y;
        const float bmx = x1.x - x3.x, bmy = x1.y - x3.y;
        spec[i0]     = make_float2(apx + bpx, apy + bpy);
        spec[i0 + 1] = make_float2(amx - bmy, amy + bmx);   // am + i*bm
        spec[i0 + 2] = make_float2(apx - bpx, apy - bpy);
        spec[i0 + 3] = make_float2(amx + bmy, amy - bmx);   // am - i*bm
    }
    __syncthreads();

    // Stages 1..5: q = 4, 16, 64, 256, 1024. Twiddles e^{+i*2*pi*tb/4096}.
#pragma unroll 1
    for (int st = 1; st < 6; st++) {
        const int q    = 1 << (2 * st);
        const int tsh  = 10 - 2 * st;       // twiddle stride shift: 1024/q
        for (int j = stid; j < M2 / 4; j += 512) {
            const int pos = j & (q - 1);
            const int i0  = ((j >> (2 * st)) << (2 * st + 2)) | pos;
            const int tb  = pos << tsh;
            float s1, c1;
            __sincosf((float)tb * (float)(2.0 * PI_D / (double)M2), &s1, &c1);
            const float2 w1 = make_float2(c1, s1);
            const float2 w2 = cmul(w1, w1);
            const float2 w3 = cmul(w2, w1);
            const float2 x0 = spec[i0];
            const float2 b  = cmul(spec[i0 + q],     w1);
            const float2 c  = cmul(spec[i0 + 2 * q], w2);
            const float2 d  = cmul(spec[i0 + 3 * q], w3);
            const float apx = x0.x + c.x, apy = x0.y + c.y;
            const float amx = x0.x - c.x, amy = x0.y - c.y;
            const float bpx = b.x + d.x,  bpy = b.y + d.y;
            const float bmx = b.x - d.x,  bmy = b.y - d.y;
            spec[i0]         = make_float2(apx + bpx, apy + bpy);
            spec[i0 + q]     = make_float2(amx - bmy, amy + bmx);
            spec[i0 + 2 * q] = make_float2(apx - bpx, apy - bpy);
            spec[i0 + 3 * q] = make_float2(amx + bmy, amy - bmx);
        }
        __syncthreads();
    }

    // z[t] = x[2t] + i*x[2t+1], already scaled. Coalesced float2 stores.
    float2* outv = (float2*)out + h * M2;
    for (int t = stid; t < M2; t += 512) {
        outv[t] = spec[t];
    }
}

// ---------------------------------------------------------------------------
extern "C" void kernel_launch(void* const* d_in, const int* in_sizes, int n_in,
                              void* d_out, int out_size)
{
    const float* w_re   = (const float*)d_in[0];
    const float* w_im   = (const float*)d_in[1];
    const float* p_re   = (const float*)d_in[2];
    const float* p_im   = (const float*)d_in[3];
    const float* B_re   = (const float*)d_in[4];
    const float* B_im   = (const float*)d_in[5];
    const float* C_re   = (const float*)d_in[6];
    const float* C_im   = (const float*)d_in[7];
    const float* log_dt = (const float*)d_in[8];

    dim3 gridA(6, HH);      // 6 blocks x 352 threads = 2112 pairs per head
    cauchy_kernel<<<gridA, 352>>>(w_re, w_im, p_re, p_im,
                                  B_re, B_im, C_re, C_im, log_dt);

    cudaFuncSetAttribute(ifft_kernel,
                         cudaFuncAttributeMaxDynamicSharedMemorySize,
                         2 * M2 * (int)sizeof(float2));
    ifft_kernel<<<HH / 2, 1024, 2 * M2 * sizeof(float2)>>>((float*)d_out);
}

// round 9
// speedup vs baseline: 1.3660x; 1.0592x over previous
#include <cuda_runtime.h>
#include <math.h>

#define HH 256
#define NP 32
#define LL 8192
#define LH 4097           // L/2 + 1
#define M2 4096           // L/2  (packed real-IFFT size)
#define ROW 4098          // padded k_f row stride (keeps rows 16B-aligned)

#ifndef PI_D
#define PI_D 3.14159265358979323846
#endif

// scratch: k_f spectrum, one padded row per head (complex)
__device__ float2 g_kf[HH * ROW];

__device__ __forceinline__ float frcp(float x) {
    float r; asm("rcp.approx.f32 %0,%1;" : "=f"(r) : "f"(x)); return r;
}

// y = 2*tan(pi*l/L); double path near the Nyquist pole where float arg error
// is amplified by 1/(pi/2 - x).
__device__ __forceinline__ float y_of(int l) {
    if (l >= LH) l = LH - 1;                 // clamp dummy lanes
    if (l < 3968) return 2.0f * tanf((float)l * (float)(PI_D / (double)LL));
    return (float)(2.0 * tan((PI_D / (double)LL) * (double)l));
}

// ---------------------------------------------------------------------------
// Cauchy evaluation for NP2 node-pairs (2*NP2 freqs) sharing one pole sweep.
// ---------------------------------------------------------------------------
template<int NP2>
__device__ __forceinline__ void cauchy_pairs(const float4 (*sh)[4],
                                             const int* pv, float2* row)
{
    const int NF = 2 * NP2;
    float y[NF];
#pragma unroll
    for (int j = 0; j < NP2; j++) {
        y[2 * j]     = y_of(2 * pv[j]);
        y[2 * j + 1] = y_of(2 * pv[j] + 1);
    }

    float r00r[NF], r00i[NF], r01r[NF], r01i[NF];
    float r10r[NF], r10i[NF], r11r[NF], r11i[NF];
#pragma unroll
    for (int f = 0; f < NF; f++) {
        r00r[f] = r00i[f] = r01r[f] = r01i[f] = 0.f;
        r10r[f] = r10i[f] = r11r[f] = r11i[f] = 0.f;
    }

#pragma unroll 2
    for (int n = 0; n < NP; n++) {
        const float4 c0 = sh[n][0];   // b, a2, s00a, s00b
        const float4 c1 = sh[n][1];   // s00c, s00d, s01a, s01b
        const float4 c2 = sh[n][2];   // s01c, s01d, s10a, s10b
        const float4 c3 = sh[n][3];   // s10c, s10d, s11a, s11b

#pragma unroll
        for (int f = 0; f < NF; f++) {
            const float t1 = y[f] - c0.x;                // y - b
            const float t2 = y[f] + c0.x;                // y + b
            const float inv1 = frcp(fmaf(t1, t1, c0.y)); // 1/(t1^2 + a^2)
            const float inv2 = frcp(fmaf(t2, t2, c0.y));
            const float u1 = t1 * inv1;
            const float u2 = t2 * inv2;
            const float Pinv = inv1 + inv2;
            const float Minv = inv2 - inv1;
            const float Pu = u1 + u2;
            const float Mu = u1 - u2;

            r00r[f] = fmaf(c0.z, Pinv, fmaf(c0.w, Mu,   r00r[f]));
            r00i[f] = fmaf(c1.x, Pu,   fmaf(c1.y, Minv, r00i[f]));
            r01r[f] = fmaf(c1.z, Pinv, fmaf(c1.w, Mu,   r01r[f]));
            r01i[f] = fmaf(c2.x, Pu,   fmaf(c2.y, Minv, r01i[f]));
            r10r[f] = fmaf(c2.z, Pinv, fmaf(c2.w, Mu,   r10r[f]));
            r10i[f] = fmaf(c3.x, Pu,   fmaf(c3.y, Minv, r10i[f]));
            r11r[f] = fmaf(c3.z, Pinv, r11r[f]);
            r11i[f] = fmaf(c3.w, Pu,   r11i[f]);
        }
    }

    // Woodbury: k_f = (r00 - r01*r10/(1+r11)) * (1 + i*y/2)   (dt already in)
#pragma unroll
    for (int j = 0; j < NP2; j++) {
        float2 res[2];
#pragma unroll
        for (int s = 0; s < 2; s++) {
            const int f = 2 * j + s;
            const float drw = 1.f + r11r[f], diw = r11i[f];
            const float invd = frcp(fmaf(drw, drw, diw * diw));
            const float numr = r01r[f] * r10r[f] - r01i[f] * r10i[f];
            const float numi = r01r[f] * r10i[f] + r01i[f] * r10r[f];
            const float cr = (numr * drw + numi * diw) * invd;
            const float ci = (numi * drw - numr * diw) * invd;
            const float ar = r00r[f] - cr, ai = r00i[f] - ci;
            const float g = 0.5f * y[f];
            res[s] = make_float2(fmaf(-ai, g, ar), fmaf(ar, g, ai));
        }
        const int p = pv[j];
        if (p < 2048) {
            *reinterpret_cast<float4*>(row + 2 * p) =
                make_float4(res[0].x, res[0].y, res[1].x, res[1].y);
        } else {
            row[2 * p] = res[0];              // l = 4096 tail, single freq
        }
    }
}

// ---------------------------------------------------------------------------
// Kernel A: grid = (4, H), block = 256. Each thread: pairs g and g+1024
// (4 freqs). Thread g==0 additionally computes pair 2048 (l=4096).
// ---------------------------------------------------------------------------
__global__ __launch_bounds__(256) void cauchy_kernel(
    const float* __restrict__ w_re, const float* __restrict__ w_im,
    const float* __restrict__ p_re, const float* __restrict__ p_im,
    const float* __restrict__ B_re, const float* __restrict__ B_im,
    const float* __restrict__ C_re, const float* __restrict__ C_im,
    const float* __restrict__ log_dt)
{
    __shared__ float4 sh[NP][4];

    const int h   = blockIdx.y;
    const int tid = threadIdx.x;

    if (tid < NP) {
        const float dt = expf(log_dt[h]);
        const int idx = h * NP + tid;
        const float a  = w_re[idx] * dt;      // fold dt into pole
        const float b  = w_im[idx] * dt;
        const float Br = B_re[idx], Bi = B_im[idx];
        const float Pr = p_re[idx], Pi = p_im[idx];
        const float Cr = C_re[idx], Ci = C_im[idx];
        const float v00r = (Br * Cr - Bi * Ci) * dt, v00i = (Br * Ci + Bi * Cr) * dt;
        const float v01r = (Br * Pr + Bi * Pi) * dt, v01i = (Bi * Pr - Br * Pi) * dt;
        const float v10r = (Pr * Cr - Pi * Ci) * dt, v10i = (Pr * Ci + Pi * Cr) * dt;
        const float v11  = (Pr * Pr + Pi * Pi) * dt;
        sh[tid][0] = make_float4(b, a * a, -a * v00r, v00i);
        sh[tid][1] = make_float4(-v00r, a * v00i, -a * v01r, v01i);
        sh[tid][2] = make_float4(-v01r, a * v01i, -a * v10r, v10i);
        sh[tid][3] = make_float4(-v10r, a * v10i, -a * v11, -v11);
    }
    __syncthreads();

    const int g = blockIdx.x * 256 + tid;     // 0..1023
    float2* row = g_kf + h * ROW;

    int pv[2] = { g, g + 1024 };              // pairs 0..2047
    cauchy_pairs<2>(sh, pv, row);

    if (g == 0) {                             // tail pair 2048 (l = 4096)
        int pt[1] = { 2048 };
        cauchy_pairs<1>(sh, pt, row);
    }
}

// ---------------------------------------------------------------------------
// FFT helpers
// ---------------------------------------------------------------------------
__device__ __forceinline__ float2 cmul(float2 a, float2 b) {
    return make_float2(a.x * b.x - a.y * b.y, a.x * b.y + a.y * b.x);
}
__device__ __forceinline__ float2 cadd(float2 a, float2 b) {
    return make_float2(a.x + b.x, a.y + b.y);
}
__device__ __forceinline__ float2 csub(float2 a, float2 b) {
    return make_float2(a.x - b.x, a.y - b.y);
}
__device__ __forceinline__ float2 cmuli(float2 a) {     // i*a
    return make_float2(-a.y, a.x);
}
__device__ __forceinline__ int rev8(int k) {  // base-8 digit reversal, 12-bit
    return ((k & 7) << 9) | (((k >> 3) & 7) << 6) | (((k >> 6) & 7) << 3) | ((k >> 9) & 7);
}
#define PAD(i) ((i) + ((i) >> 3))             // smem skew: 4096 -> 4608 slots

// ---------------------------------------------------------------------------
// Kernel B: irfft(k_f), ONE head per 512-thread block, radix-8 DIT
// (4 stages, 3 barriers), last stage writes gmem from registers.
// grid = 256, block = 512, 36 KB dynamic shared (under 48 KB default).
// ---------------------------------------------------------------------------
__global__ __launch_bounds__(512) void ifft_kernel(float* __restrict__ out)
{
    extern __shared__ float2 spec[];          // 4608 float2 (36 KB)

    const int stid = threadIdx.x;             // 0..511
    const int h    = blockIdx.x;

    // Hermitian pack with 1/M scale folded in, base-8 digit-reversed layout.
    const float sc = 0.5f / (float)M2;
    const float2* kf = g_kf + h * ROW;
    for (int k = stid; k <= M2 / 2; k += 512) {
        const float2 Xk = kf[k];
        const float2 Xm = kf[M2 - k];
        const float mr = Xm.x, mi = -Xm.y;            // conj(X[M-k])
        const float Er = sc * (Xk.x + mr);
        const float Ei = sc * (Xk.y + mi);
        const float Fr = sc * (Xk.x - mr);
        const float Fi = sc * (Xk.y - mi);
        float s, c;
        __sincosf((float)k * (float)(PI_D / (double)M2), &s, &c); // e^{+i*pi*k/M}
        const float Or = c * Fr - s * Fi;
        const float Oi = c * Fi + s * Fr;
        spec[PAD(rev8(k))] = make_float2(Er - Oi, Ei + Or);
        if (k > 0 && k < M2 / 2) {
            spec[PAD(rev8(M2 - k))] = make_float2(Er + Oi, Or - Ei);
        }
    }
    __syncthreads();

    const float C8 = 0.70710678118654752f;    // sqrt(2)/2
    float2* outv = (float2*)out + h * M2;

    // 4 radix-8 stages: q = 1, 8, 64, 512. 512 butterflies/stage, 1/thread.
#pragma unroll 1
    for (int st = 0; st < 4; st++) {
        const int lq = 3 * st;                // log8 shift
        const int q  = 1 << lq;
        const int j  = stid;
        const int pos = j & (q - 1);
        const int i0  = ((j >> lq) << (lq + 3)) | pos;

        float2 v[8];
#pragma unroll
        for (int m = 0; m < 8; m++) v[m] = spec[PAD(i0 + m * q)];

        if (st > 0) {
            // external twiddles: v[m] *= e^{+2*pi*i*m*pos/(8q)}
            float s1, c1;
            __sincosf((float)pos * (float)(2.0 * PI_D / (8.0 * (double)q)), &s1, &c1);
            const float2 w1 = make_float2(c1, s1);
            const float2 w2 = cmul(w1, w1);
            const float2 w3 = cmul(w2, w1);
            const float2 w4 = cmul(w2, w2);
            const float2 w5 = cmul(w2, w3);
            const float2 w6 = cmul(w3, w3);
            const float2 w7 = cmul(w3, w4);
            v[1] = cmul(v[1], w1); v[2] = cmul(v[2], w2); v[3] = cmul(v[3], w3);
            v[4] = cmul(v[4], w4); v[5] = cmul(v[5], w5); v[6] = cmul(v[6], w6);
            v[7] = cmul(v[7], w7);
        }

        // inverse DFT8: even DFT4 (v0,v2,v4,v6), odd DFT4 (v1,v3,v5,v7), combine
        const float2 es = cadd(v[0], v[4]), ed = csub(v[0], v[4]);
        const float2 fs = cadd(v[2], v[6]), fd = csub(v[2], v[6]);
        const float2 E0 = cadd(es, fs);
        const float2 E1 = cadd(ed, cmuli(fd));
        const float2 E2 = csub(es, fs);
        const float2 E3 = csub(ed, cmuli(fd));

        const float2 os = cadd(v[1], v[5]), od = csub(v[1], v[5]);
        const float2 ps = cadd(v[3], v[7]), pd = csub(v[3], v[7]);
        const float2 O0 = cadd(os, ps);
        const float2 O1 = cadd(od, cmuli(pd));
        const float2 O2 = csub(os, ps);
        const float2 O3 = csub(od, cmuli(pd));

        // W8^m * O[m]:  W8^1=c(1+i), W8^2=i, W8^3=c(-1+i)
        const float2 T1 = make_float2(C8 * (O1.x - O1.y), C8 * (O1.x + O1.y));
        const float2 T2 = cmuli(O2);
        const float2 T3 = make_float2(C8 * (-O3.x - O3.y), C8 * (O3.x - O3.y));

        float2 X[8];
        X[0] = cadd(E0, O0);  X[4] = csub(E0, O0);
        X[1] = cadd(E1, T1);  X[5] = csub(E1, T1);
        X[2] = cadd(E2, T2);  X[6] = csub(E2, T2);
        X[3] = cadd(E3, T3);  X[7] = csub(E3, T3);

        if (st < 3) {
#pragma unroll
            for (int m = 0; m < 8; m++) spec[PAD(i0 + m * q)] = X[m];
            __syncthreads();
        } else {
            // q = 512, i0 = j: z[t] = x[2t] + i*x[2t+1], already scaled.
#pragma unroll
            for (int m = 0; m < 8; m++) outv[i0 + m * 512] = X[m];
        }
    }
}

// ---------------------------------------------------------------------------
extern "C" void kernel_launch(void* const* d_in, const int* in_sizes, int n_in,
                              void* d_out, int out_size)
{
    const float* w_re   = (const float*)d_in[0];
    const float* w_im   = (const float*)d_in[1];
    const float* p_re   = (const float*)d_in[2];
    const float* p_im   = (const float*)d_in[3];
    const float* B_re   = (const float*)d_in[4];
    const float* B_im   = (const float*)d_in[5];
    const float* C_re   = (const float*)d_in[6];
    const float* C_im   = (const float*)d_in[7];
    const float* log_dt = (const float*)d_in[8];

    dim3 gridA(4, HH);      // 4 blocks x 256 threads x 2 pairs per head
    cauchy_kernel<<<gridA, 256>>>(w_re, w_im, p_re, p_im,
                                  B_re, B_im, C_re, C_im, log_dt);

    ifft_kernel<<<HH, 512, 4608 * sizeof(float2)>>>((float*)d_out);
}